// round 15
// baseline (speedup 1.0000x reference)
#include <cuda_runtime.h>
#include <cuda_bf16.h>
#include <cstdint>
#include <cstring>

// Problem constants
#define B   32
#define DE  256
#define T   32
#define C   128
#define HW  16384   // 128*128

// ===========================================================================
// Helpers
// ===========================================================================
__device__ __forceinline__ void ldsm4(uint32_t& r0, uint32_t& r1,
                                      uint32_t& r2, uint32_t& r3, uint32_t addr) {
    asm volatile("ldmatrix.sync.aligned.m8n8.x4.shared.b16 {%0,%1,%2,%3}, [%4];"
                 : "=r"(r0), "=r"(r1), "=r"(r2), "=r"(r3) : "r"(addr));
}

__device__ __forceinline__ void mma_bf16(float& d0, float& d1, float& d2, float& d3,
                                         uint32_t a0, uint32_t a1, uint32_t a2, uint32_t a3,
                                         uint32_t b0, uint32_t b1) {
    asm volatile(
        "mma.sync.aligned.m16n8k16.row.col.f32.bf16.bf16.f32 "
        "{%0,%1,%2,%3}, {%4,%5,%6,%7}, {%8,%9}, {%0,%1,%2,%3};"
        : "+f"(d0), "+f"(d1), "+f"(d2), "+f"(d3)
        : "r"(a0), "r"(a1), "r"(a2), "r"(a3), "r"(b0), "r"(b1));
}

__device__ __forceinline__ uint32_t smem_to_u32(const void* smem_ptr) {
    uint32_t addr;
    asm("{ .reg .u64 tmp; cvta.to.shared.u64 tmp, %1; cvt.u32.u64 %0, tmp; }"
        : "=r"(addr) : "l"(smem_ptr));
    return addr;
}

__device__ __forceinline__ float2 ffma2(float2 a, float2 b, float2 c) {
    unsigned long long ua, ub, uc, ud;
    memcpy(&ua, &a, 8); memcpy(&ub, &b, 8); memcpy(&uc, &c, 8);
    asm("fma.rn.f32x2 %0, %1, %2, %3;" : "=l"(ud) : "l"(ua), "l"(ub), "l"(uc));
    float2 d; memcpy(&d, &ud, 8);
    return d;
}

__device__ __forceinline__ uint32_t pack2(__nv_bfloat16 lo, __nv_bfloat16 hi) {
    __nv_bfloat162 v; v.x = lo; v.y = hi;   // .x = lower K index
    uint32_t u; memcpy(&u, &v, 4);
    return u;
}

__device__ __forceinline__ void split_bf16(float x, __nv_bfloat16& hi, __nv_bfloat16& lo) {
    hi = __float2bfloat16_rn(x);
    lo = __float2bfloat16_rn(x - __bfloat162float(hi));
}

__device__ __forceinline__ void split2(float2 v, uint32_t& hi, uint32_t& lo) {
    __nv_bfloat16 h0, h1, l0, l1;
    split_bf16(v.x, h0, l0);
    split_bf16(v.y, h1, l1);
    hi = pack2(h0, h1);
    lo = pack2(l0, l1);
}

// Streaming (evict-first) vector store: out lines are written once, never
// re-read. (Loads must stay default-policy: h lines are re-hit across k.)
__device__ __forceinline__ void stg4_cs(float* p, float4 v) {
    asm volatile("st.global.cs.v4.f32 [%0], {%1, %2, %3, %4};"
                 :: "l"(p), "f"(v.x), "f"(v.y), "f"(v.z), "f"(v.w) : "memory");
}

__device__ __forceinline__ void prefetch_l2(const void* p) {
    asm volatile("prefetch.global.L2 [%0];" :: "l"(p));
}

#define CP_ASYNC16(dst, src) \
    asm volatile("cp.async.cg.shared.global [%0], [%1], 16;" \
                 :: "r"(dst), "l"(src) : "memory")
#define CP_ASYNC_COMMIT() asm volatile("cp.async.commit_group;" ::: "memory")
#define CP_ASYNC_WAIT0()  asm volatile("cp.async.wait_group 0;" ::: "memory")

// ===========================================================================
// Global scratch: e_ in bf16 hi/lo splits, both orientations, with the MMA
// index permutations PRE-APPLIED (see prep_kernel).
// ===========================================================================
__device__ __nv_bfloat16 g_eS_hi[B * T * C];
__device__ __nv_bfloat16 g_eS_lo[B * T * C];
__device__ __nv_bfloat16 g_eC_hi[B * C * T];
__device__ __nv_bfloat16 g_eC_lo[B * C * T];

// Score-GEMM K permutation (see R9).
__device__ __forceinline__ int permS(int c) {
    const int r  = c & 15;
    const int tg = r >> 2;
    const int j  = r & 3;
    const int p  = (j < 2) ? (2 * tg + j) : (8 + 2 * tg + (j - 2));
    return (c & ~15) | p;
}
// Ctx-GEMM N permutation (see R9).
__device__ __forceinline__ int permC(int c) {
    const int r  = c & 31;
    const int tg = r >> 3;
    const int q  = r & 7;
    const int nt = q >> 1;
    const int j  = q & 1;
    return (c & ~31) | (nt * 8 + 2 * tg + j);
}

// ---------------------------------------------------------------------------
// Prep kernel: e_[c][t] projection (fp32 accum), bf16 hi/lo split, permuted
// stores. grid (4,B), block 256. Unroll 32 -> 8 exposed L2-latency waves.
// eC stores packed as single 8-byte stores (4 contiguous t's).
// ---------------------------------------------------------------------------
__global__ __launch_bounds__(256)
void prep_kernel(const float* __restrict__ e,
                 const float* __restrict__ Wd,
                 const float* __restrict__ bias) {
    __shared__ float e_sm[DE * T];  // 32 KB, [d][t]
    const int b   = blockIdx.y;
    const int tid = threadIdx.x;

    const float4* e4  = reinterpret_cast<const float4*>(e + b * DE * T);
    float4*       es4 = reinterpret_cast<float4*>(e_sm);
#pragma unroll
    for (int i = 0; i < DE * T / 4 / 256; i++)
        es4[i * 256 + tid] = e4[i * 256 + tid];
    __syncthreads();

    const int c  = blockIdx.x * 32 + (tid & 31);
    const int t0 = (tid >> 5) * 4;
    const int cS = permS(c);
    const int cC = permC(c);

    float2 acc0 = make_float2(0.f, 0.f), acc1 = make_float2(0.f, 0.f);
#pragma unroll 32
    for (int d = 0; d < DE; d++) {
        const float w = __ldg(&Wd[d * C + c]);
        const float4 ev = *reinterpret_cast<const float4*>(e_sm + d * T + t0);
        const float2 w2 = make_float2(w, w);
        acc0 = ffma2(w2, make_float2(ev.x, ev.y), acc0);
        acc1 = ffma2(w2, make_float2(ev.z, ev.w), acc1);
    }

    const float bc = bias[c];
    float xs[4] = { acc0.x + bc, acc0.y + bc, acc1.x + bc, acc1.y + bc };
    __nv_bfloat16 hi4[4], lo4[4];
#pragma unroll
    for (int i = 0; i < 4; i++) split_bf16(xs[i], hi4[i], lo4[i]);

    // eS: scattered 2B stores (stride C between t's)
#pragma unroll
    for (int i = 0; i < 4; i++) {
        const int t = t0 + i;
        g_eS_hi[(b * T + t) * C + cS] = hi4[i];
        g_eS_lo[(b * T + t) * C + cS] = lo4[i];
    }
    // eC: 4 contiguous t's -> one 8B store each for hi and lo
    {
        const uint32_t h0 = pack2(hi4[0], hi4[1]);
        const uint32_t h1 = pack2(hi4[2], hi4[3]);
        const uint32_t l0 = pack2(lo4[0], lo4[1]);
        const uint32_t l1 = pack2(lo4[2], lo4[3]);
        uint2* pH = reinterpret_cast<uint2*>(&g_eC_hi[(b * C + cC) * T + t0]);
        uint2* pL = reinterpret_cast<uint2*>(&g_eC_lo[(b * C + cC) * T + t0]);
        *pH = make_uint2(h0, h1);
        *pL = make_uint2(l0, l1);
    }
}

// ---------------------------------------------------------------------------
// Attention kernel (R10-proven configuration + next-tile L2 prefetch):
// TWO 64-pixel tiles per block, 128 threads (4 warps, 16px/warp/tile).
// h read directly from gmem (default policy) as float4 A-fragments
// (K-permuted e_S); ctx channels N-permuted -> float4 .cs stores.
// Single cp.async group, one barrier. 4 CTAs/SM.
// ---------------------------------------------------------------------------

#define STR_HC  272   // eS row stride (bytes), conflict-free LDSM (proven)
#define STR_EC  80    // eC row stride (bytes)

#define SH_ES_HI 0                    // 32 x 272 = 8704
#define SH_ES_LO 8704                 // 8704
#define SH_EC_HI 17408                // 128 x 80 = 10240
#define SH_EC_LO 27648                // 10240
#define SMEM_TOTAL 37888

__global__ __launch_bounds__(128, 4)
void attn_kernel(const float* __restrict__ h, float* __restrict__ out) {
    __shared__ char smem[SMEM_TOTAL];
    const uint32_t sbase = smem_to_u32(smem);

    const int tid  = threadIdx.x;
    const int warp = tid >> 5;
    const int lane = tid & 31;
    const int b    = blockIdx.y;

    // ---- Async-stage e_S tiles ([t][c] bf16, hi+lo; K-permuted) ----
    {
        const char* ehS = reinterpret_cast<const char*>(g_eS_hi + b * T * C);
        const char* elS = reinterpret_cast<const char*>(g_eS_lo + b * T * C);
#pragma unroll
        for (int i = 0; i < 4; i++) {             // 512 chunks / 128 threads
            const int idx = i * 128 + tid;
            const int t   = idx >> 4;
            const int c16 = idx & 15;
            const uint32_t dst = sbase + (uint32_t)(t * STR_HC + c16 * 16);
            const int      src = t * 256 + c16 * 16;
            CP_ASYNC16(dst + SH_ES_HI, ehS + src);
            CP_ASYNC16(dst + SH_ES_LO, elS + src);
        }
    }
    // ---- Async-stage e_C tiles ([c][t] bf16, hi+lo; N-permuted) ----
    {
        const char* ehC = reinterpret_cast<const char*>(g_eC_hi + b * C * T);
        const char* elC = reinterpret_cast<const char*>(g_eC_lo + b * C * T);
#pragma unroll
        for (int i = 0; i < 4; i++) {             // 512 chunks / 128 threads
            const int idx = i * 128 + tid;
            const int c   = idx >> 2;
            const int u   = idx & 3;
            const uint32_t dst = sbase + (uint32_t)(c * STR_EC + u * 16);
            const int      src = c * 64 + u * 16;
            CP_ASYNC16(dst + SH_EC_HI, ehC + src);
            CP_ASYNC16(dst + SH_EC_LO, elC + src);
        }
    }
    CP_ASYNC_COMMIT();
    CP_ASYNC_WAIT0();
    __syncthreads();   // the only barrier in the kernel

    const int g  = lane >> 2;     // fragment row group
    const int tg = lane & 3;      // fragment col group

    const uint32_t bRow = (uint32_t)(8 * (lane >> 4) + (lane & 7));
    const uint32_t bCol = (uint32_t)(((lane >> 3) & 1) * 16);
    const uint32_t bBaseS = sbase + SH_ES_HI + bRow * STR_HC + bCol;

    const size_t r8o = (size_t)8 * C;                // +8 pixel rows (h)
    const size_t r8d = (size_t)8 * 2 * C;            // +8 pixel rows (out)
    float* outB = out + (size_t)(b * HW) * 2 * C;

#pragma unroll 1
    for (int tt = 0; tt < 2; tt++) {
        const int p0   = (blockIdx.x * 2 + tt) * 64;
        const int prow = p0 + warp * 16 + g;         // pixel row for a0/a2

        const float* hr  = h    + (size_t)(b * HW + prow) * C + tg * 4;
        float*       orp = outB + (size_t)prow * 2 * C + C + tg * 4;

        // ---- Score GEMM: S[16,32] in 4 n-tiles of m16n8 fragments. ----
        float sd[4][4];
#pragma unroll
        for (int nt = 0; nt < 4; nt++)
#pragma unroll
            for (int q = 0; q < 4; q++) sd[nt][q] = 0.0f;

#pragma unroll
        for (int k = 0; k < 8; k++) {             // K=128 in steps of 16
            const int kc = k * 16;
            const float4 v0 = *reinterpret_cast<const float4*>(hr + kc);        // row g
            const float4 v1 = *reinterpret_cast<const float4*>(hr + r8o + kc);  // row g+8
            // fused concat copy: out[..., C:2C] = h (original channel order)
            stg4_cs(orp + kc, v0);
            stg4_cs(orp + r8d + kc, v1);

            uint32_t aH[4], aL[4];
            split2(make_float2(v0.x, v0.y), aH[0], aL[0]);
            split2(make_float2(v1.x, v1.y), aH[1], aL[1]);
            split2(make_float2(v0.z, v0.w), aH[2], aL[2]);
            split2(make_float2(v1.z, v1.w), aH[3], aL[3]);

            const uint32_t bAddr = bBaseS + (uint32_t)(k * 32);
            uint32_t bH[8], bL[8];
            ldsm4(bH[0], bH[1], bH[2], bH[3], bAddr);                    // t 0-15
            ldsm4(bH[4], bH[5], bH[6], bH[7], bAddr + 16 * STR_HC);      // t 16-31
            ldsm4(bL[0], bL[1], bL[2], bL[3], bAddr + (SH_ES_LO - SH_ES_HI));
            ldsm4(bL[4], bL[5], bL[6], bL[7], bAddr + (SH_ES_LO - SH_ES_HI) + 16 * STR_HC);
#pragma unroll
            for (int nt = 0; nt < 4; nt++) {
                const uint32_t bh0 = bH[nt * 2], bh1 = bH[nt * 2 + 1];
                const uint32_t bl0 = bL[nt * 2], bl1 = bL[nt * 2 + 1];
                mma_bf16(sd[nt][0], sd[nt][1], sd[nt][2], sd[nt][3],
                         aH[0], aH[1], aH[2], aH[3], bh0, bh1);          // hi*hi
                mma_bf16(sd[nt][0], sd[nt][1], sd[nt][2], sd[nt][3],
                         aL[0], aL[1], aL[2], aL[3], bh0, bh1);          // lo*hi
                mma_bf16(sd[nt][0], sd[nt][1], sd[nt][2], sd[nt][3],
                         aH[0], aH[1], aH[2], aH[3], bl0, bl1);          // hi*lo
            }
        }

        // ---- Prefetch next tile's h into L2 (~1-2us ahead of its use) ----
        if (tt == 0) {
            const char* nb = reinterpret_cast<const char*>(
                h + (size_t)(b * HW + (blockIdx.x * 2 + 1) * 64) * C);
            prefetch_l2(nb + (size_t)(tid)       * 128);
            prefetch_l2(nb + (size_t)(128 + tid) * 128);
        }

        // ---- Softmax over t (rows g and g+8) ----
        float er[8], eh8[8];
#pragma unroll
        for (int nt = 0; nt < 4; nt++) {
            er[2 * nt]      = sd[nt][0];
            er[2 * nt + 1]  = sd[nt][1];
            eh8[2 * nt]     = sd[nt][2];
            eh8[2 * nt + 1] = sd[nt][3];
        }
        float m0 = er[0], m1 = eh8[0];
#pragma unroll
        for (int i = 1; i < 8; i++) { m0 = fmaxf(m0, er[i]); m1 = fmaxf(m1, eh8[i]); }
        m0 = fmaxf(m0, __shfl_xor_sync(0xFFFFFFFFu, m0, 1));
        m0 = fmaxf(m0, __shfl_xor_sync(0xFFFFFFFFu, m0, 2));
        m1 = fmaxf(m1, __shfl_xor_sync(0xFFFFFFFFu, m1, 1));
        m1 = fmaxf(m1, __shfl_xor_sync(0xFFFFFFFFu, m1, 2));

        float s0 = 0.0f, s1 = 0.0f;
#pragma unroll
        for (int i = 0; i < 8; i++) {
            er[i]  = __expf(er[i] - m0);  s0 += er[i];
            eh8[i] = __expf(eh8[i] - m1); s1 += eh8[i];
        }
        s0 += __shfl_xor_sync(0xFFFFFFFFu, s0, 1);
        s0 += __shfl_xor_sync(0xFFFFFFFFu, s0, 2);
        s1 += __shfl_xor_sync(0xFFFFFFFFu, s1, 1);
        s1 += __shfl_xor_sync(0xFFFFFFFFu, s1, 2);
        const float inv0 = 1.0f / s0;
        const float inv1 = 1.0f / s1;
#pragma unroll
        for (int i = 0; i < 8; i++) { er[i] *= inv0; eh8[i] *= inv1; }

        // Beta directly as MMA A fragments (k = t), hi/lo split, 2 k-steps.
        uint32_t bAH[2][4], bAL[2][4];
#pragma unroll
        for (int ks = 0; ks < 2; ks++) {
            const int base = ks * 4;
            split2(make_float2(er[base],      er[base + 1]),  bAH[ks][0], bAL[ks][0]);
            split2(make_float2(eh8[base],     eh8[base + 1]), bAH[ks][1], bAL[ks][1]);
            split2(make_float2(er[base + 2],  er[base + 3]),  bAH[ks][2], bAL[ks][2]);
            split2(make_float2(eh8[base + 2], eh8[base + 3]), bAH[ks][3], bAL[ks][3]);
        }

        // ---- Context GEMM: Ctx[16,128] in 4 chunks of 32 channels ----
#pragma unroll
        for (int chunk = 0; chunk < 4; chunk++) {
            float cd[4][4];
#pragma unroll
            for (int nt = 0; nt < 4; nt++)
#pragma unroll
                for (int q = 0; q < 4; q++) cd[nt][q] = 0.0f;

#pragma unroll
            for (int ks = 0; ks < 2; ks++) {
                const uint32_t bAddr = sbase + SH_EC_HI
                    + (uint32_t)(chunk * 32 + bRow) * STR_EC + bCol + (uint32_t)(ks * 32);
                uint32_t bH[8], bL[8];
                ldsm4(bH[0], bH[1], bH[2], bH[3], bAddr);                    // c-tiles 0,1
                ldsm4(bH[4], bH[5], bH[6], bH[7], bAddr + 16 * STR_EC);      // c-tiles 2,3
                ldsm4(bL[0], bL[1], bL[2], bL[3], bAddr + (SH_EC_LO - SH_EC_HI));
                ldsm4(bL[4], bL[5], bL[6], bL[7], bAddr + (SH_EC_LO - SH_EC_HI) + 16 * STR_EC);
#pragma unroll
                for (int nt = 0; nt < 4; nt++) {
                    const uint32_t bh0 = bH[nt * 2], bh1 = bH[nt * 2 + 1];
                    const uint32_t bl0 = bL[nt * 2], bl1 = bL[nt * 2 + 1];
                    mma_bf16(cd[nt][0], cd[nt][1], cd[nt][2], cd[nt][3],
                             bAH[ks][0], bAH[ks][1], bAH[ks][2], bAH[ks][3], bh0, bh1);
                    mma_bf16(cd[nt][0], cd[nt][1], cd[nt][2], cd[nt][3],
                             bAL[ks][0], bAL[ks][1], bAL[ks][2], bAL[ks][3], bh0, bh1);
                    mma_bf16(cd[nt][0], cd[nt][1], cd[nt][2], cd[nt][3],
                             bAH[ks][0], bAH[ks][1], bAH[ks][2], bAH[ks][3], bl0, bl1);
                }
            }

            // N-permuted -> lane holds channels chunk*32 + 8tg..+7, contiguous.
            const int cbase = chunk * 32 + 8 * tg;
            float* r0p = outB + (size_t)prow * 2 * C + cbase;
            float* r1p = outB + (size_t)(prow + 8) * 2 * C + cbase;
            stg4_cs(r0p,     make_float4(cd[0][0], cd[0][1], cd[1][0], cd[1][1]));
            stg4_cs(r0p + 4, make_float4(cd[2][0], cd[2][1], cd[3][0], cd[3][1]));
            stg4_cs(r1p,     make_float4(cd[0][2], cd[0][3], cd[1][2], cd[1][3]));
            stg4_cs(r1p + 4, make_float4(cd[2][2], cd[2][3], cd[3][2], cd[3][3]));
        }
    }
}

// ---------------------------------------------------------------------------
extern "C" void kernel_launch(void* const* d_in, const int* in_sizes, int n_in,
                              void* d_out, int out_size) {
    const float* e    = (const float*)d_in[0];  // [B, DE, T]
    const float* h    = (const float*)d_in[1];  // [B, H, W, C]
    const float* Wd   = (const float*)d_in[2];  // [DE, C]
    const float* bias = (const float*)d_in[3];  // [C]
    float* out = (float*)d_out;                 // [B, H, W, 2C]

    prep_kernel<<<dim3(4, B), 256>>>(e, Wd, bias);
    attn_kernel<<<dim3(HW / 128, B), 128>>>(h, out);
}

// round 16
// speedup vs baseline: 1.1369x; 1.1369x over previous
#include <cuda_runtime.h>
#include <cuda_bf16.h>
#include <cstdint>
#include <cstring>

// Problem constants
#define B   32
#define DE  256
#define T   32
#define C   128
#define HW  16384   // 128*128

// ===========================================================================
// Helpers
// ===========================================================================
__device__ __forceinline__ void ldsm4(uint32_t& r0, uint32_t& r1,
                                      uint32_t& r2, uint32_t& r3, uint32_t addr) {
    asm volatile("ldmatrix.sync.aligned.m8n8.x4.shared.b16 {%0,%1,%2,%3}, [%4];"
                 : "=r"(r0), "=r"(r1), "=r"(r2), "=r"(r3) : "r"(addr));
}

__device__ __forceinline__ void mma_bf16(float& d0, float& d1, float& d2, float& d3,
                                         uint32_t a0, uint32_t a1, uint32_t a2, uint32_t a3,
                                         uint32_t b0, uint32_t b1) {
    asm volatile(
        "mma.sync.aligned.m16n8k16.row.col.f32.bf16.bf16.f32 "
        "{%0,%1,%2,%3}, {%4,%5,%6,%7}, {%8,%9}, {%0,%1,%2,%3};"
        : "+f"(d0), "+f"(d1), "+f"(d2), "+f"(d3)
        : "r"(a0), "r"(a1), "r"(a2), "r"(a3), "r"(b0), "r"(b1));
}

__device__ __forceinline__ uint32_t smem_to_u32(const void* smem_ptr) {
    uint32_t addr;
    asm("{ .reg .u64 tmp; cvta.to.shared.u64 tmp, %1; cvt.u32.u64 %0, tmp; }"
        : "=r"(addr) : "l"(smem_ptr));
    return addr;
}

__device__ __forceinline__ float2 ffma2(float2 a, float2 b, float2 c) {
    unsigned long long ua, ub, uc, ud;
    memcpy(&ua, &a, 8); memcpy(&ub, &b, 8); memcpy(&uc, &c, 8);
    asm("fma.rn.f32x2 %0, %1, %2, %3;" : "=l"(ud) : "l"(ua), "l"(ub), "l"(uc));
    float2 d; memcpy(&d, &ud, 8);
    return d;
}

__device__ __forceinline__ uint32_t pack2(__nv_bfloat16 lo, __nv_bfloat16 hi) {
    __nv_bfloat162 v; v.x = lo; v.y = hi;   // .x = lower K index
    uint32_t u; memcpy(&u, &v, 4);
    return u;
}

__device__ __forceinline__ void split_bf16(float x, __nv_bfloat16& hi, __nv_bfloat16& lo) {
    hi = __float2bfloat16_rn(x);
    lo = __float2bfloat16_rn(x - __bfloat162float(hi));
}

__device__ __forceinline__ void split2(float2 v, uint32_t& hi, uint32_t& lo) {
    __nv_bfloat16 h0, h1, l0, l1;
    split_bf16(v.x, h0, l0);
    split_bf16(v.y, h1, l1);
    hi = pack2(h0, h1);
    lo = pack2(l0, l1);
}

// Streaming (evict-first) vector store: out lines are written once, never
// re-read. (Loads stay default-policy: h lines are re-hit across k.)
__device__ __forceinline__ void stg4_cs(float* p, float4 v) {
    asm volatile("st.global.cs.v4.f32 [%0], {%1, %2, %3, %4};"
                 :: "l"(p), "f"(v.x), "f"(v.y), "f"(v.z), "f"(v.w) : "memory");
}

#define CP_ASYNC16(dst, src) \
    asm volatile("cp.async.cg.shared.global [%0], [%1], 16;" \
                 :: "r"(dst), "l"(src) : "memory")
#define CP_ASYNC_COMMIT() asm volatile("cp.async.commit_group;" ::: "memory")
#define CP_ASYNC_WAIT0()  asm volatile("cp.async.wait_group 0;" ::: "memory")

// ===========================================================================
// Global scratch: e_ in bf16 hi/lo splits, both orientations, with the MMA
// index permutations PRE-APPLIED (see prep_kernel).
// ===========================================================================
__device__ __nv_bfloat16 g_eS_hi[B * T * C];
__device__ __nv_bfloat16 g_eS_lo[B * T * C];
__device__ __nv_bfloat16 g_eC_hi[B * C * T];
__device__ __nv_bfloat16 g_eC_lo[B * C * T];

// Score-GEMM K permutation (see R9).
__device__ __forceinline__ int permS(int c) {
    const int r  = c & 15;
    const int tg = r >> 2;
    const int j  = r & 3;
    const int p  = (j < 2) ? (2 * tg + j) : (8 + 2 * tg + (j - 2));
    return (c & ~15) | p;
}
// Ctx-GEMM N permutation (see R9).
__device__ __forceinline__ int permC(int c) {
    const int r  = c & 31;
    const int tg = r >> 3;
    const int q  = r & 7;
    const int nt = q >> 1;
    const int j  = q & 1;
    return (c & ~31) | (nt * 8 + 2 * tg + j);
}

// ---------------------------------------------------------------------------
// Prep kernel: e_[c][t] projection (fp32 accum), bf16 hi/lo split, permuted
// stores. grid (4,B), block 256. Unroll 32 -> 8 exposed L2-latency waves.
// eC stores packed as single 8-byte stores (4 contiguous t's).
// ---------------------------------------------------------------------------
__global__ __launch_bounds__(256)
void prep_kernel(const float* __restrict__ e,
                 const float* __restrict__ Wd,
                 const float* __restrict__ bias) {
    __shared__ float e_sm[DE * T];  // 32 KB, [d][t]
    const int b   = blockIdx.y;
    const int tid = threadIdx.x;

    const float4* e4  = reinterpret_cast<const float4*>(e + b * DE * T);
    float4*       es4 = reinterpret_cast<float4*>(e_sm);
#pragma unroll
    for (int i = 0; i < DE * T / 4 / 256; i++)
        es4[i * 256 + tid] = e4[i * 256 + tid];
    __syncthreads();

    const int c  = blockIdx.x * 32 + (tid & 31);
    const int t0 = (tid >> 5) * 4;
    const int cS = permS(c);
    const int cC = permC(c);

    float2 acc0 = make_float2(0.f, 0.f), acc1 = make_float2(0.f, 0.f);
#pragma unroll 32
    for (int d = 0; d < DE; d++) {
        const float w = __ldg(&Wd[d * C + c]);
        const float4 ev = *reinterpret_cast<const float4*>(e_sm + d * T + t0);
        const float2 w2 = make_float2(w, w);
        acc0 = ffma2(w2, make_float2(ev.x, ev.y), acc0);
        acc1 = ffma2(w2, make_float2(ev.z, ev.w), acc1);
    }

    const float bc = bias[c];
    float xs[4] = { acc0.x + bc, acc0.y + bc, acc1.x + bc, acc1.y + bc };
    __nv_bfloat16 hi4[4], lo4[4];
#pragma unroll
    for (int i = 0; i < 4; i++) split_bf16(xs[i], hi4[i], lo4[i]);

    // eS: scattered 2B stores (stride C between t's)
#pragma unroll
    for (int i = 0; i < 4; i++) {
        const int t = t0 + i;
        g_eS_hi[(b * T + t) * C + cS] = hi4[i];
        g_eS_lo[(b * T + t) * C + cS] = lo4[i];
    }
    // eC: 4 contiguous t's -> one 8B store each for hi and lo
    {
        const uint32_t h0 = pack2(hi4[0], hi4[1]);
        const uint32_t h1 = pack2(hi4[2], hi4[3]);
        const uint32_t l0 = pack2(lo4[0], lo4[1]);
        const uint32_t l1 = pack2(lo4[2], lo4[3]);
        uint2* pH = reinterpret_cast<uint2*>(&g_eC_hi[(b * C + cC) * T + t0]);
        uint2* pL = reinterpret_cast<uint2*>(&g_eC_lo[(b * C + cC) * T + t0]);
        *pH = make_uint2(h0, h1);
        *pL = make_uint2(l0, l1);
    }
}

// ---------------------------------------------------------------------------
// Attention kernel (byte-exact R10/R14 configuration — best measured,
// 131.5us): TWO 64-pixel tiles per block, 128 threads (4 warps, 16px/warp/
// tile). h read directly from gmem (default policy) as float4 A-fragments
// (K-permuted e_S); ctx channels N-permuted -> float4 .cs stores.
// Single cp.async group, one barrier. 4 CTAs/SM. NO prefetch, NO .cs loads.
// ---------------------------------------------------------------------------

#define STR_HC  272   // eS row stride (bytes), conflict-free LDSM (proven)
#define STR_EC  80    // eC row stride (bytes)

#define SH_ES_HI 0                    // 32 x 272 = 8704
#define SH_ES_LO 8704                 // 8704
#define SH_EC_HI 17408                // 128 x 80 = 10240
#define SH_EC_LO 27648                // 10240
#define SMEM_TOTAL 37888

__global__ __launch_bounds__(128, 4)
void attn_kernel(const float* __restrict__ h, float* __restrict__ out) {
    __shared__ char smem[SMEM_TOTAL];
    const uint32_t sbase = smem_to_u32(smem);

    const int tid  = threadIdx.x;
    const int warp = tid >> 5;
    const int lane = tid & 31;
    const int b    = blockIdx.y;

    // ---- Async-stage e_S tiles ([t][c] bf16, hi+lo; K-permuted) ----
    {
        const char* ehS = reinterpret_cast<const char*>(g_eS_hi + b * T * C);
        const char* elS = reinterpret_cast<const char*>(g_eS_lo + b * T * C);
#pragma unroll
        for (int i = 0; i < 4; i++) {             // 512 chunks / 128 threads
            const int idx = i * 128 + tid;
            const int t   = idx >> 4;
            const int c16 = idx & 15;
            const uint32_t dst = sbase + (uint32_t)(t * STR_HC + c16 * 16);
            const int      src = t * 256 + c16 * 16;
            CP_ASYNC16(dst + SH_ES_HI, ehS + src);
            CP_ASYNC16(dst + SH_ES_LO, elS + src);
        }
    }
    // ---- Async-stage e_C tiles ([c][t] bf16, hi+lo; N-permuted) ----
    {
        const char* ehC = reinterpret_cast<const char*>(g_eC_hi + b * C * T);
        const char* elC = reinterpret_cast<const char*>(g_eC_lo + b * C * T);
#pragma unroll
        for (int i = 0; i < 4; i++) {             // 512 chunks / 128 threads
            const int idx = i * 128 + tid;
            const int c   = idx >> 2;
            const int u   = idx & 3;
            const uint32_t dst = sbase + (uint32_t)(c * STR_EC + u * 16);
            const int      src = c * 64 + u * 16;
            CP_ASYNC16(dst + SH_EC_HI, ehC + src);
            CP_ASYNC16(dst + SH_EC_LO, elC + src);
        }
    }
    CP_ASYNC_COMMIT();
    CP_ASYNC_WAIT0();
    __syncthreads();   // the only barrier in the kernel

    const int g  = lane >> 2;     // fragment row group
    const int tg = lane & 3;      // fragment col group

    const uint32_t bRow = (uint32_t)(8 * (lane >> 4) + (lane & 7));
    const uint32_t bCol = (uint32_t)(((lane >> 3) & 1) * 16);
    const uint32_t bBaseS = sbase + SH_ES_HI + bRow * STR_HC + bCol;

    const size_t r8o = (size_t)8 * C;                // +8 pixel rows (h)
    const size_t r8d = (size_t)8 * 2 * C;            // +8 pixel rows (out)
    float* outB = out + (size_t)(b * HW) * 2 * C;

#pragma unroll 1
    for (int tt = 0; tt < 2; tt++) {
        const int p0   = (blockIdx.x * 2 + tt) * 64;
        const int prow = p0 + warp * 16 + g;         // pixel row for a0/a2

        const float* hr  = h    + (size_t)(b * HW + prow) * C + tg * 4;
        float*       orp = outB + (size_t)prow * 2 * C + C + tg * 4;

        // ---- Score GEMM: S[16,32] in 4 n-tiles of m16n8 fragments. ----
        float sd[4][4];
#pragma unroll
        for (int nt = 0; nt < 4; nt++)
#pragma unroll
            for (int q = 0; q < 4; q++) sd[nt][q] = 0.0f;

#pragma unroll
        for (int k = 0; k < 8; k++) {             // K=128 in steps of 16
            const int kc = k * 16;
            const float4 v0 = *reinterpret_cast<const float4*>(hr + kc);        // row g
            const float4 v1 = *reinterpret_cast<const float4*>(hr + r8o + kc);  // row g+8
            // fused concat copy: out[..., C:2C] = h (original channel order)
            stg4_cs(orp + kc, v0);
            stg4_cs(orp + r8d + kc, v1);

            uint32_t aH[4], aL[4];
            split2(make_float2(v0.x, v0.y), aH[0], aL[0]);
            split2(make_float2(v1.x, v1.y), aH[1], aL[1]);
            split2(make_float2(v0.z, v0.w), aH[2], aL[2]);
            split2(make_float2(v1.z, v1.w), aH[3], aL[3]);

            const uint32_t bAddr = bBaseS + (uint32_t)(k * 32);
            uint32_t bH[8], bL[8];
            ldsm4(bH[0], bH[1], bH[2], bH[3], bAddr);                    // t 0-15
            ldsm4(bH[4], bH[5], bH[6], bH[7], bAddr + 16 * STR_HC);      // t 16-31
            ldsm4(bL[0], bL[1], bL[2], bL[3], bAddr + (SH_ES_LO - SH_ES_HI));
            ldsm4(bL[4], bL[5], bL[6], bL[7], bAddr + (SH_ES_LO - SH_ES_HI) + 16 * STR_HC);
#pragma unroll
            for (int nt = 0; nt < 4; nt++) {
                const uint32_t bh0 = bH[nt * 2], bh1 = bH[nt * 2 + 1];
                const uint32_t bl0 = bL[nt * 2], bl1 = bL[nt * 2 + 1];
                mma_bf16(sd[nt][0], sd[nt][1], sd[nt][2], sd[nt][3],
                         aH[0], aH[1], aH[2], aH[3], bh0, bh1);          // hi*hi
                mma_bf16(sd[nt][0], sd[nt][1], sd[nt][2], sd[nt][3],
                         aL[0], aL[1], aL[2], aL[3], bh0, bh1);          // lo*hi
                mma_bf16(sd[nt][0], sd[nt][1], sd[nt][2], sd[nt][3],
                         aH[0], aH[1], aH[2], aH[3], bl0, bl1);          // hi*lo
            }
        }

        // ---- Softmax over t (rows g and g+8) ----
        float er[8], eh8[8];
#pragma unroll
        for (int nt = 0; nt < 4; nt++) {
            er[2 * nt]      = sd[nt][0];
            er[2 * nt + 1]  = sd[nt][1];
            eh8[2 * nt]     = sd[nt][2];
            eh8[2 * nt + 1] = sd[nt][3];
        }
        float m0 = er[0], m1 = eh8[0];
#pragma unroll
        for (int i = 1; i < 8; i++) { m0 = fmaxf(m0, er[i]); m1 = fmaxf(m1, eh8[i]); }
        m0 = fmaxf(m0, __shfl_xor_sync(0xFFFFFFFFu, m0, 1));
        m0 = fmaxf(m0, __shfl_xor_sync(0xFFFFFFFFu, m0, 2));
        m1 = fmaxf(m1, __shfl_xor_sync(0xFFFFFFFFu, m1, 1));
        m1 = fmaxf(m1, __shfl_xor_sync(0xFFFFFFFFu, m1, 2));

        float s0 = 0.0f, s1 = 0.0f;
#pragma unroll
        for (int i = 0; i < 8; i++) {
            er[i]  = __expf(er[i] - m0);  s0 += er[i];
            eh8[i] = __expf(eh8[i] - m1); s1 += eh8[i];
        }
        s0 += __shfl_xor_sync(0xFFFFFFFFu, s0, 1);
        s0 += __shfl_xor_sync(0xFFFFFFFFu, s0, 2);
        s1 += __shfl_xor_sync(0xFFFFFFFFu, s1, 1);
        s1 += __shfl_xor_sync(0xFFFFFFFFu, s1, 2);
        const float inv0 = 1.0f / s0;
        const float inv1 = 1.0f / s1;
#pragma unroll
        for (int i = 0; i < 8; i++) { er[i] *= inv0; eh8[i] *= inv1; }

        // Beta directly as MMA A fragments (k = t), hi/lo split, 2 k-steps.
        uint32_t bAH[2][4], bAL[2][4];
#pragma unroll
        for (int ks = 0; ks < 2; ks++) {
            const int base = ks * 4;
            split2(make_float2(er[base],      er[base + 1]),  bAH[ks][0], bAL[ks][0]);
            split2(make_float2(eh8[base],     eh8[base + 1]), bAH[ks][1], bAL[ks][1]);
            split2(make_float2(er[base + 2],  er[base + 3]),  bAH[ks][2], bAL[ks][2]);
            split2(make_float2(eh8[base + 2], eh8[base + 3]), bAH[ks][3], bAL[ks][3]);
        }

        // ---- Context GEMM: Ctx[16,128] in 4 chunks of 32 channels ----
#pragma unroll
        for (int chunk = 0; chunk < 4; chunk++) {
            float cd[4][4];
#pragma unroll
            for (int nt = 0; nt < 4; nt++)
#pragma unroll
                for (int q = 0; q < 4; q++) cd[nt][q] = 0.0f;

#pragma unroll
            for (int ks = 0; ks < 2; ks++) {
                const uint32_t bAddr = sbase + SH_EC_HI
                    + (uint32_t)(chunk * 32 + bRow) * STR_EC + bCol + (uint32_t)(ks * 32);
                uint32_t bH[8], bL[8];
                ldsm4(bH[0], bH[1], bH[2], bH[3], bAddr);                    // c-tiles 0,1
                ldsm4(bH[4], bH[5], bH[6], bH[7], bAddr + 16 * STR_EC);      // c-tiles 2,3
                ldsm4(bL[0], bL[1], bL[2], bL[3], bAddr + (SH_EC_LO - SH_EC_HI));
                ldsm4(bL[4], bL[5], bL[6], bL[7], bAddr + (SH_EC_LO - SH_EC_HI) + 16 * STR_EC);
#pragma unroll
                for (int nt = 0; nt < 4; nt++) {
                    const uint32_t bh0 = bH[nt * 2], bh1 = bH[nt * 2 + 1];
                    const uint32_t bl0 = bL[nt * 2], bl1 = bL[nt * 2 + 1];
                    mma_bf16(cd[nt][0], cd[nt][1], cd[nt][2], cd[nt][3],
                             bAH[ks][0], bAH[ks][1], bAH[ks][2], bAH[ks][3], bh0, bh1);
                    mma_bf16(cd[nt][0], cd[nt][1], cd[nt][2], cd[nt][3],
                             bAL[ks][0], bAL[ks][1], bAL[ks][2], bAL[ks][3], bh0, bh1);
                    mma_bf16(cd[nt][0], cd[nt][1], cd[nt][2], cd[nt][3],
                             bAH[ks][0], bAH[ks][1], bAH[ks][2], bAH[ks][3], bl0, bl1);
                }
            }

            // N-permuted -> lane holds channels chunk*32 + 8tg..+7, contiguous.
            const int cbase = chunk * 32 + 8 * tg;
            float* r0p = outB + (size_t)prow * 2 * C + cbase;
            float* r1p = outB + (size_t)(prow + 8) * 2 * C + cbase;
            stg4_cs(r0p,     make_float4(cd[0][0], cd[0][1], cd[1][0], cd[1][1]));
            stg4_cs(r0p + 4, make_float4(cd[2][0], cd[2][1], cd[3][0], cd[3][1]));
            stg4_cs(r1p,     make_float4(cd[0][2], cd[0][3], cd[1][2], cd[1][3]));
            stg4_cs(r1p + 4, make_float4(cd[2][2], cd[2][3], cd[3][2], cd[3][3]));
        }
    }
}

// ---------------------------------------------------------------------------
extern "C" void kernel_launch(void* const* d_in, const int* in_sizes, int n_in,
                              void* d_out, int out_size) {
    const float* e    = (const float*)d_in[0];  // [B, DE, T]
    const float* h    = (const float*)d_in[1];  // [B, H, W, C]
    const float* Wd   = (const float*)d_in[2];  // [DE, C]
    const float* bias = (const float*)d_in[3];  // [C]
    float* out = (float*)d_out;                 // [B, H, W, 2C]

    prep_kernel<<<dim3(4, B), 256>>>(e, Wd, bias);
    attn_kernel<<<dim3(HW / 128, B), 128>>>(h, out);
}